// round 3
// baseline (speedup 1.0000x reference)
#include <cuda_runtime.h>
#include <math.h>

// Shapes fixed by the problem: B=4, C=256, H=W=64, N=4096, Ci=128
#define B_  4
#define C_  256
#define N_  4096
#define CI_ 128

// Scratch (allocation-free rule: __device__ globals)
__device__ float g_xbar[B_ * C_];   // per-(b,c) spatial mean of x
__device__ float g_w[B_ * C_];      // w[b,c] = sum_k tbar[b,k] * phi_w[k,c]
__device__ float g_s[B_];           // s[b]  = sum_k tbar[b,k] * phi_b[k]

// ---------------------------------------------------------------------------
// Kernel 1: xbar[b,c] = mean_j x[b,c,j].  One block per (b,c) row.
// 4096 floats per row, float4 loads, block reduce.
// ---------------------------------------------------------------------------
__global__ __launch_bounds__(128) void k_rowmean(const float* __restrict__ x) {
    const int row = blockIdx.x;              // b*C_ + c
    const float4* xr = (const float4*)(x + (size_t)row * N_);
    const int tid = threadIdx.x;

    float acc = 0.f;
    #pragma unroll
    for (int i = 0; i < N_ / 4 / 128; ++i) {     // 8 iterations
        float4 v = xr[tid + i * 128];
        acc += v.x + v.y + v.z + v.w;
    }
    // warp reduce
    #pragma unroll
    for (int o = 16; o; o >>= 1) acc += __shfl_xor_sync(0xffffffffu, acc, o);
    __shared__ float warp_s[4];
    if ((tid & 31) == 0) warp_s[tid >> 5] = acc;
    __syncthreads();
    if (tid == 0) {
        float s = warp_s[0] + warp_s[1] + warp_s[2] + warp_s[3];
        g_xbar[row] = s * (1.0f / N_);
    }
}

// ---------------------------------------------------------------------------
// Kernel 2 (tiny): per batch b:
//   tbar[k] = theta_b[k] + sum_c theta_w[k,c] * xbar[b,c]      (128 dots of 256)
//   w[b,c]  = sum_k tbar[k] * phi_w[k,c]                        (256 dots of 128)
//   s[b]    = sum_k tbar[k] * phi_b[k]
// One block of 256 threads per batch.
// ---------------------------------------------------------------------------
__global__ __launch_bounds__(256) void k_small(const float* __restrict__ theta_w,
                                               const float* __restrict__ theta_b,
                                               const float* __restrict__ phi_w,
                                               const float* __restrict__ phi_b) {
    const int b = blockIdx.x;
    const int tid = threadIdx.x;
    const int warp = tid >> 5, lane = tid & 31;

    __shared__ float xb[C_];
    __shared__ float tb[CI_];

    xb[tid] = g_xbar[b * C_ + tid];
    __syncthreads();

    // Phase 1: 8 warps, 128 k values -> 16 k per warp; lane-parallel over c.
    for (int i = 0; i < CI_ / 8; ++i) {
        int k = warp * (CI_ / 8) + i;
        const float* tw = theta_w + (size_t)k * C_;
        float a = 0.f;
        #pragma unroll
        for (int c = lane; c < C_; c += 32) a += tw[c] * xb[c];
        #pragma unroll
        for (int o = 16; o; o >>= 1) a += __shfl_xor_sync(0xffffffffu, a, o);
        if (lane == 0) tb[k] = a + theta_b[k];
    }
    __syncthreads();

    // Phase 2: thread c computes w[b,c] (coalesced over phi_w columns).
    float wacc = 0.f;
    #pragma unroll 8
    for (int k = 0; k < CI_; ++k) wacc += tb[k] * phi_w[(size_t)k * C_ + tid];
    g_w[b * C_ + tid] = wacc;

    // s[b]: warp 0 reduces tb . phi_b
    if (warp == 0) {
        float a = 0.f;
        #pragma unroll
        for (int k = lane; k < CI_; k += 32) a += tb[k] * phi_b[k];
        #pragma unroll
        for (int o = 16; o; o >>= 1) a += __shfl_xor_sync(0xffffffffu, a, o);
        if (lane == 0) g_s[b] = a;
    }
}

// ---------------------------------------------------------------------------
// Kernel 3: per pixel j:
//   m    = (sum_c w[b,c]*x[b,c,j] + s[b]) / N
//   conf = sigmoid(m)
//   out[b,c,j] = conf * x[b,c,j]   for all c
// Block = 128 threads = 128 pixels; loop c twice (2nd loop hits L2/L1).
// Grid (N_/128, B_) = (32, 4) = 128 blocks.
// ---------------------------------------------------------------------------
__global__ __launch_bounds__(128) void k_pixel(const float* __restrict__ x,
                                               float* __restrict__ out) {
    const int b = blockIdx.y;
    const int j = blockIdx.x * 128 + threadIdx.x;
    const int tid = threadIdx.x;

    __shared__ float ws[C_];
    #pragma unroll
    for (int c = tid; c < C_; c += 128) ws[c] = g_w[b * C_ + c];
    __syncthreads();

    const float* xb = x + (size_t)b * C_ * N_;
    float acc = 0.f;
    #pragma unroll 8
    for (int c = 0; c < C_; ++c)
        acc += ws[c] * __ldg(xb + (size_t)c * N_ + j);

    float m = (acc + g_s[b]) * (1.0f / N_);
    float conf = 1.0f / (1.0f + expf(-m));

    float* ob = out + (size_t)b * C_ * N_;
    #pragma unroll 8
    for (int c = 0; c < C_; ++c)
        ob[(size_t)c * N_ + j] = conf * __ldg(xb + (size_t)c * N_ + j);
}

// ---------------------------------------------------------------------------
extern "C" void kernel_launch(void* const* d_in, const int* in_sizes, int n_in,
                              void* d_out, int out_size) {
    const float* x       = (const float*)d_in[0];
    const float* theta_w = (const float*)d_in[1];
    const float* theta_b = (const float*)d_in[2];
    const float* phi_w   = (const float*)d_in[3];
    const float* phi_b   = (const float*)d_in[4];
    float* out = (float*)d_out;

    k_rowmean<<<B_ * C_, 128>>>(x);
    k_small<<<B_, 256>>>(theta_w, theta_b, phi_w, phi_b);
    k_pixel<<<dim3(N_ / 128, B_), 128>>>(x, out);
}

// round 5
// speedup vs baseline: 1.5070x; 1.5070x over previous
#include <cuda_runtime.h>
#include <math.h>

// Shapes fixed by the problem: B=4, C=256, H=W=64, N=4096, Ci=128
#define B_  4
#define C_  256
#define N_  4096
#define CI_ 128

// Scratch (allocation-free rule: __device__ globals)
__device__ float g_xbar[B_ * C_];   // per-(b,c) spatial mean of x
__device__ float g_w[B_ * C_];      // w[b,c] = sum_k tbar[b,k] * phi_w[k,c]
__device__ float g_s[B_];           // s[b]  = sum_k tbar[b,k] * phi_b[k]

// ---------------------------------------------------------------------------
// Kernel 1: xbar[b,c] = mean_j x[b,c,j].  One block (256 thr) per (b,c) row.
// 4096 floats per row -> 4 float4 per thread.
// ---------------------------------------------------------------------------
__global__ __launch_bounds__(256) void k_rowmean(const float* __restrict__ x) {
    const int row = blockIdx.x;              // b*C_ + c
    const float4* xr = (const float4*)(x + (size_t)row * N_);
    const int tid = threadIdx.x;

    float acc = 0.f;
    #pragma unroll
    for (int i = 0; i < N_ / 4 / 256; ++i) {     // 4 iterations
        float4 v = xr[tid + i * 256];
        acc += v.x + v.y + v.z + v.w;
    }
    #pragma unroll
    for (int o = 16; o; o >>= 1) acc += __shfl_xor_sync(0xffffffffu, acc, o);
    __shared__ float warp_s[8];
    if ((tid & 31) == 0) warp_s[tid >> 5] = acc;
    __syncthreads();
    if (tid == 0) {
        float s = 0.f;
        #pragma unroll
        for (int i = 0; i < 8; ++i) s += warp_s[i];
        g_xbar[row] = s * (1.0f / N_);
    }
}

// ---------------------------------------------------------------------------
// Kernel 2 (tiny): per batch b:
//   tbar[k] = theta_b[k] + sum_c theta_w[k,c] * xbar[b,c]
//   w[b,c]  = sum_k tbar[k] * phi_w[k,c]
//   s[b]    = sum_k tbar[k] * phi_b[k]
// ---------------------------------------------------------------------------
__global__ __launch_bounds__(256) void k_small(const float* __restrict__ theta_w,
                                               const float* __restrict__ theta_b,
                                               const float* __restrict__ phi_w,
                                               const float* __restrict__ phi_b) {
    const int b = blockIdx.x;
    const int tid = threadIdx.x;
    const int warp = tid >> 5, lane = tid & 31;

    __shared__ float xb[C_];
    __shared__ float tb[CI_];

    xb[tid] = g_xbar[b * C_ + tid];
    __syncthreads();

    for (int i = 0; i < CI_ / 8; ++i) {
        int k = warp * (CI_ / 8) + i;
        const float* tw = theta_w + (size_t)k * C_;
        float a = 0.f;
        #pragma unroll
        for (int c = lane; c < C_; c += 32) a += tw[c] * xb[c];
        #pragma unroll
        for (int o = 16; o; o >>= 1) a += __shfl_xor_sync(0xffffffffu, a, o);
        if (lane == 0) tb[k] = a + theta_b[k];
    }
    __syncthreads();

    float wacc = 0.f;
    #pragma unroll 8
    for (int k = 0; k < CI_; ++k) wacc += tb[k] * phi_w[(size_t)k * C_ + tid];
    g_w[b * C_ + tid] = wacc;

    if (warp == 0) {
        float a = 0.f;
        #pragma unroll
        for (int k = lane; k < CI_; k += 32) a += tb[k] * phi_b[k];
        #pragma unroll
        for (int o = 16; o; o >>= 1) a += __shfl_xor_sync(0xffffffffu, a, o);
        if (lane == 0) g_s[b] = a;
    }
}

// ---------------------------------------------------------------------------
// Kernel 3 (fused dot + scale, single read of x):
// Block = 512 threads = (64 pixels) x (8 channel-splits of 32 channels each).
// Each thread loads its 32 x values ONCE into registers, computes its partial
// dot with w, shared-reduces over the 8 splits -> conf[j], then writes
// conf * xv[i] straight from registers. Grid (64 j-tiles, B).
// ---------------------------------------------------------------------------
#define TJ_   64
#define CSPL_ 8
#define CPT_  (C_ / CSPL_)   // 32 channels per thread

__global__ __launch_bounds__(512, 2) void k_fused(const float* __restrict__ x,
                                                  float* __restrict__ out) {
    const int b    = blockIdx.y;
    const int tid  = threadIdx.x;
    const int jloc = tid & (TJ_ - 1);
    const int csub = tid >> 6;                  // 0..7
    const int j    = blockIdx.x * TJ_ + jloc;

    __shared__ float ws[C_];
    __shared__ float part[CSPL_ * TJ_];
    __shared__ float conf_s[TJ_];

    if (tid < C_) ws[tid] = g_w[b * C_ + tid];
    __syncthreads();

    const float* xb = x + (size_t)b * C_ * N_ + j;
    float xv[CPT_];
    float acc = 0.f;
    #pragma unroll
    for (int i = 0; i < CPT_; ++i) {
        const int c = csub * CPT_ + i;
        xv[i] = __ldg(xb + (size_t)c * N_);
        acc += ws[c] * xv[i];
    }
    part[csub * TJ_ + jloc] = acc;
    __syncthreads();

    if (tid < TJ_) {
        float m = 0.f;
        #pragma unroll
        for (int k = 0; k < CSPL_; ++k) m += part[k * TJ_ + tid];
        m = (m + g_s[b]) * (1.0f / N_);
        conf_s[tid] = 1.0f / (1.0f + expf(-m));
    }
    __syncthreads();

    const float conf = conf_s[jloc];
    float* ob = out + (size_t)b * C_ * N_ + j;
    #pragma unroll
    for (int i = 0; i < CPT_; ++i) {
        const int c = csub * CPT_ + i;
        ob[(size_t)c * N_] = conf * xv[i];
    }
}

// ---------------------------------------------------------------------------
extern "C" void kernel_launch(void* const* d_in, const int* in_sizes, int n_in,
                              void* d_out, int out_size) {
    const float* x       = (const float*)d_in[0];
    const float* theta_w = (const float*)d_in[1];
    const float* theta_b = (const float*)d_in[2];
    const float* phi_w   = (const float*)d_in[3];
    const float* phi_b   = (const float*)d_in[4];
    float* out = (float*)d_out;

    k_rowmean<<<B_ * C_, 256>>>(x);
    k_small<<<B_, 256>>>(theta_w, theta_b, phi_w, phi_b);
    k_fused<<<dim3(N_ / TJ_, B_), 512>>>(x, out);
}